// round 1
// baseline (speedup 1.0000x reference)
#include <cuda_runtime.h>
#include <cuda_bf16.h>
#include <math.h>

// ---------------- problem constants ----------------
#define Vv 8192
#define LABn 64
#define Cc 512
#define Hh 16
#define HSs 32
#define Ll 12
#define FFf 2048
#define Bb 8
#define Tt 1024
#define BT (Bb*Tt)              // 8192
#define BTV ((size_t)BT * Vv)   // 67108864

// ---------------- scratch (device globals, no allocation) ----------------
__device__ float g_x [BT*Cc];
__device__ float g_h [BT*Cc];
__device__ float g_q [BT*Cc];
__device__ float g_k [BT*Cc];
__device__ float g_v [BT*Cc];
__device__ float g_o [BT*Cc];
__device__ float g_ff[BT*FFf];
__device__ float g_wq[Ll*Cc*Cc];
__device__ float g_wk[Ll*Cc*Cc];
__device__ float g_wv[Ll*Cc*Cc];
__device__ float g_loss;

// ---------------- pack Wq/Wk/Wv [L,H,C,HS] -> [L,C,H*HS] ----------------
__global__ void pack_qkv(const float* __restrict__ Wq, const float* __restrict__ Wk,
                         const float* __restrict__ Wv) {
    const int n = Ll*Hh*Cc*HSs;
    for (int gid = blockIdx.x*blockDim.x + threadIdx.x; gid < n; gid += gridDim.x*blockDim.x) {
        int d = gid & (HSs-1);
        int c = (gid >> 5) & (Cc-1);
        int h = (gid >> 14) & (Hh-1);
        int l = gid >> 18;
        int dst = l*Cc*Cc + c*Cc + h*HSs + d;
        g_wq[dst] = Wq[gid];
        g_wk[dst] = Wk[gid];
        g_wv[dst] = Wv[gid];
    }
}

// ---------------- embedding ----------------
__global__ __launch_bounds__(128) void embed_k(const int* __restrict__ idx,
                                               const int* __restrict__ lab,
                                               const float* __restrict__ tok_emb,
                                               const float* __restrict__ lab_emb,
                                               const float* __restrict__ pos_emb) {
    int i = blockIdx.x;              // 0..BT-1
    int t = i & (Tt-1);
    int ix = idx[i];
    int lb = lab[i];
    const float4* te = (const float4*)(tok_emb + (size_t)ix*Cc);
    const float4* le = (const float4*)(lab_emb + (size_t)lb*Cc);
    const float4* pe = (const float4*)(pos_emb + (size_t)t *Cc);
    float4* xo = (float4*)(g_x + (size_t)i*Cc);
    int c = threadIdx.x;             // 128 threads * float4 = 512 floats
    float4 a = te[c], b = le[c], p = pe[c];
    xo[c] = make_float4(a.x+b.x+p.x, a.y+b.y+p.y, a.z+b.z+p.z, a.w+b.w+p.w);
}

// ---------------- layernorm (one block per row, 128 threads) ----------------
__global__ __launch_bounds__(128) void lnorm_k(const float* __restrict__ x,
                                               const float* __restrict__ g,
                                               const float* __restrict__ b,
                                               float* __restrict__ y) {
    int row = blockIdx.x;
    const float4* xr = (const float4*)(x + (size_t)row*Cc);
    float4 v = xr[threadIdx.x];
    float s  = v.x+v.y+v.z+v.w;
    float s2 = v.x*v.x + v.y*v.y + v.z*v.z + v.w*v.w;
    // warp reduce
    for (int o = 16; o > 0; o >>= 1) {
        s  += __shfl_down_sync(0xffffffff, s,  o);
        s2 += __shfl_down_sync(0xffffffff, s2, o);
    }
    __shared__ float sh[4], sh2[4];
    int wid = threadIdx.x >> 5, lane = threadIdx.x & 31;
    if (lane == 0) { sh[wid] = s; sh2[wid] = s2; }
    __syncthreads();
    __shared__ float smean, srstd;
    if (threadIdx.x == 0) {
        float ts = sh[0]+sh[1]+sh[2]+sh[3];
        float ts2 = sh2[0]+sh2[1]+sh2[2]+sh2[3];
        float mean = ts * (1.0f/Cc);
        float var = ts2 * (1.0f/Cc) - mean*mean;
        smean = mean;
        srstd = rsqrtf(var + 1e-5f);
    }
    __syncthreads();
    float mean = smean, rstd = srstd;
    int c = threadIdx.x * 4;
    float4 gg = *(const float4*)(g + c);
    float4 bb = *(const float4*)(b + c);
    float4 out;
    out.x = (v.x-mean)*rstd*gg.x + bb.x;
    out.y = (v.y-mean)*rstd*gg.y + bb.y;
    out.z = (v.z-mean)*rstd*gg.z + bb.z;
    out.w = (v.w-mean)*rstd*gg.w + bb.w;
    ((float4*)(y + (size_t)row*Cc))[threadIdx.x] = out;
}

// ---------------- SGEMM 128x128x8, 8x8 per thread ----------------
// C = [res +] A@B [+ bias] [relu]; all dims multiples of tile sizes.
template<bool BIAS, bool RELU, bool RES>
__global__ __launch_bounds__(256) void sgemm_k(const float* __restrict__ A,
                                               const float* __restrict__ Bm,
                                               const float* __restrict__ bias,
                                               const float* __restrict__ res,
                                               float* __restrict__ Cm,
                                               int M, int N, int K) {
    __shared__ float As[8][128];
    __shared__ float Bs[8][128];
    int tid = threadIdx.x;
    int tx = tid & 15, ty = tid >> 4;
    int row0 = blockIdx.y * 128, col0 = blockIdx.x * 128;
    float acc[8][8];
    #pragma unroll
    for (int i = 0; i < 8; i++)
        #pragma unroll
        for (int j = 0; j < 8; j++) acc[i][j] = 0.f;

    int arow = tid >> 1;
    int akq  = (tid & 1) * 4;
    int brow = tid >> 5;
    int bcol = (tid & 31) * 4;
    const float* Aptr = A + (size_t)(row0 + arow) * K + akq;
    const float* Bptr = Bm + (size_t)brow * N + col0 + bcol;

    for (int kt = 0; kt < K; kt += 8) {
        float4 a4 = *(const float4*)(Aptr + kt);
        As[akq+0][arow] = a4.x;
        As[akq+1][arow] = a4.y;
        As[akq+2][arow] = a4.z;
        As[akq+3][arow] = a4.w;
        float4 b4 = *(const float4*)(Bptr + (size_t)kt * N);
        *(float4*)&Bs[brow][bcol] = b4;
        __syncthreads();
        #pragma unroll
        for (int k = 0; k < 8; k++) {
            float ar[8], br[8];
            *(float4*)&ar[0] = *(const float4*)&As[k][ty*8];
            *(float4*)&ar[4] = *(const float4*)&As[k][ty*8+4];
            *(float4*)&br[0] = *(const float4*)&Bs[k][tx*8];
            *(float4*)&br[4] = *(const float4*)&Bs[k][tx*8+4];
            #pragma unroll
            for (int i = 0; i < 8; i++)
                #pragma unroll
                for (int j = 0; j < 8; j++)
                    acc[i][j] = fmaf(ar[i], br[j], acc[i][j]);
        }
        __syncthreads();
    }

    #pragma unroll
    for (int i = 0; i < 8; i++) {
        int r = row0 + ty*8 + i;
        #pragma unroll
        for (int jv = 0; jv < 2; jv++) {
            int cbase = col0 + tx*8 + jv*4;
            float4 v;
            v.x = acc[i][jv*4+0]; v.y = acc[i][jv*4+1];
            v.z = acc[i][jv*4+2]; v.w = acc[i][jv*4+3];
            if (BIAS) {
                float4 bb = *(const float4*)(bias + cbase);
                v.x += bb.x; v.y += bb.y; v.z += bb.z; v.w += bb.w;
            }
            if (RELU) {
                v.x = fmaxf(v.x, 0.f); v.y = fmaxf(v.y, 0.f);
                v.z = fmaxf(v.z, 0.f); v.w = fmaxf(v.w, 0.f);
            }
            if (RES) {
                float4 rr = *(const float4*)(res + (size_t)r*N + cbase);
                v.x += rr.x; v.y += rr.y; v.z += rr.z; v.w += rr.w;
            }
            *(float4*)(Cm + (size_t)r*N + cbase) = v;
        }
    }
}

// ---------------- causal flash attention (1 thread = 1 query row) ----------------
__global__ __launch_bounds__(128) void attn_k(const float* __restrict__ q,
                                              const float* __restrict__ k,
                                              const float* __restrict__ v,
                                              float* __restrict__ o) {
    __shared__ float Ksh[64][HSs];
    __shared__ float Vsh[64][HSs];
    int bh = blockIdx.y;
    int b = bh >> 4, h = bh & 15;
    int qi = blockIdx.x * 128 + threadIdx.x;
    const float scale = 0.17677669529663689f;  // 32^-0.5

    float qr[HSs];
    {
        const float4* qp = (const float4*)(q + (size_t)(b*Tt + qi)*Cc + h*HSs);
        #pragma unroll
        for (int i = 0; i < 8; i++) *(float4*)&qr[i*4] = qp[i];
    }
    float m = -1e30f, ssum = 0.f;
    float acc[HSs];
    #pragma unroll
    for (int d = 0; d < HSs; d++) acc[d] = 0.f;

    int ntiles = (blockIdx.x + 1) * 2;   // key tiles of 64 covering [0, q0+128)
    for (int kt = 0; kt < ntiles; kt++) {
        int kbase = kt * 64;
        #pragma unroll
        for (int i = 0; i < 4; i++) {
            int f = threadIdx.x + i * 128;       // 0..511 float4 slots
            int r = f >> 3, d4 = (f & 7) << 2;
            size_t gi = (size_t)(b*Tt + kbase + r)*Cc + h*HSs + d4;
            *(float4*)&Ksh[r][d4] = *(const float4*)(k + gi);
            *(float4*)&Vsh[r][d4] = *(const float4*)(v + gi);
        }
        __syncthreads();

        float sj[64];
        float tm = -1e30f;
        #pragma unroll
        for (int j = 0; j < 64; j++) {
            float s = -1e30f;
            if (kbase + j <= qi) {
                float dsum = 0.f;
                #pragma unroll
                for (int d = 0; d < HSs; d++) dsum = fmaf(qr[d], Ksh[j][d], dsum);
                s = dsum * scale;
                tm = fmaxf(tm, s);
            }
            sj[j] = s;
        }
        if (tm > -1e29f) {
            float mn = fmaxf(m, tm);
            float corr = __expf(m - mn);
            ssum *= corr;
            #pragma unroll
            for (int d = 0; d < HSs; d++) acc[d] *= corr;
            #pragma unroll
            for (int j = 0; j < 64; j++) {
                float p = __expf(sj[j] - mn);
                ssum += p;
                #pragma unroll
                for (int d = 0; d < HSs; d++) acc[d] = fmaf(p, Vsh[j][d], acc[d]);
            }
            m = mn;
        }
        __syncthreads();
    }
    float inv = 1.f / ssum;
    float* op = o + (size_t)(b*Tt + qi)*Cc + h*HSs;
    #pragma unroll
    for (int i = 0; i < 8; i++) {
        float4 w;
        w.x = acc[i*4+0]*inv; w.y = acc[i*4+1]*inv;
        w.z = acc[i*4+2]*inv; w.w = acc[i*4+3]*inv;
        *(float4*)(op + i*4) = w;
    }
}

// ---------------- loss ----------------
__global__ void zero_loss_k() { g_loss = 0.f; }

__global__ __launch_bounds__(256) void loss_k(const float* __restrict__ logits,
                                              const int* __restrict__ targets) {
    int row = blockIdx.x;
    const float* lr = logits + (size_t)row * Vv;
    float mx = -1e30f;
    for (int i = threadIdx.x; i < Vv; i += 256) mx = fmaxf(mx, lr[i]);
    for (int o = 16; o > 0; o >>= 1) mx = fmaxf(mx, __shfl_down_sync(0xffffffff, mx, o));
    __shared__ float shm[8];
    int wid = threadIdx.x >> 5, lane = threadIdx.x & 31;
    if (lane == 0) shm[wid] = mx;
    __syncthreads();
    __shared__ float rowmax;
    if (threadIdx.x == 0) {
        float t = shm[0];
        for (int i = 1; i < 8; i++) t = fmaxf(t, shm[i]);
        rowmax = t;
    }
    __syncthreads();
    float rm = rowmax;
    float se = 0.f;
    for (int i = threadIdx.x; i < Vv; i += 256) se += __expf(lr[i] - rm);
    for (int o = 16; o > 0; o >>= 1) se += __shfl_down_sync(0xffffffff, se, o);
    if (lane == 0) shm[wid] = se;
    __syncthreads();
    if (threadIdx.x == 0) {
        float t = 0.f;
        for (int i = 0; i < 8; i++) t += shm[i];
        float lp = lr[targets[row]] - rm - logf(t);
        atomicAdd(&g_loss, lp);
    }
}

__global__ void finalize_k(float* out, int extra) {
    float lv = -g_loss / (float)BT;
    for (int i = threadIdx.x + blockIdx.x*blockDim.x; i < extra; i += blockDim.x*gridDim.x)
        out[BTV + i] = lv;
}

// ---------------- host launcher ----------------
static void* symaddr(const void* sym) {
    void* p = nullptr;
    cudaGetSymbolAddress(&p, sym);
    return p;
}

extern "C" void kernel_launch(void* const* d_in, const int* in_sizes, int n_in,
                              void* d_out, int out_size) {
    const int*   idx      = (const int*)  d_in[0];
    const int*   idx_lab  = (const int*)  d_in[1];
    const int*   targets  = (const int*)  d_in[2];
    const float* tok_emb  = (const float*)d_in[3];
    const float* pos_emb  = (const float*)d_in[4];
    const float* lab_emb  = (const float*)d_in[5];
    const float* Wq       = (const float*)d_in[6];
    const float* Wk       = (const float*)d_in[7];
    const float* Wv       = (const float*)d_in[8];
    const float* Wo       = (const float*)d_in[9];
    const float* bo       = (const float*)d_in[10];
    const float* ln1_g    = (const float*)d_in[11];
    const float* ln1_b    = (const float*)d_in[12];
    const float* W1       = (const float*)d_in[13];
    const float* b1       = (const float*)d_in[14];
    const float* W2       = (const float*)d_in[15];
    const float* b2       = (const float*)d_in[16];
    const float* ln2_g    = (const float*)d_in[17];
    const float* ln2_b    = (const float*)d_in[18];
    const float* lnf_g    = (const float*)d_in[19];
    const float* lnf_b    = (const float*)d_in[20];
    const float* Wlm      = (const float*)d_in[21];
    const float* blm      = (const float*)d_in[22];
    float* out = (float*)d_out;

    float* x  = (float*)symaddr(g_x);
    float* h  = (float*)symaddr(g_h);
    float* q  = (float*)symaddr(g_q);
    float* k  = (float*)symaddr(g_k);
    float* v  = (float*)symaddr(g_v);
    float* o  = (float*)symaddr(g_o);
    float* ff = (float*)symaddr(g_ff);
    float* wq = (float*)symaddr(g_wq);
    float* wk = (float*)symaddr(g_wk);
    float* wv = (float*)symaddr(g_wv);

    // pack QKV weights
    pack_qkv<<<2048, 256>>>(Wq, Wk, Wv);

    // embedding
    embed_k<<<BT, 128>>>(idx, idx_lab, tok_emb, lab_emb, pos_emb);

    dim3 g512 (Cc/128,  BT/128);   // (4, 64)
    dim3 g2048(FFf/128, BT/128);   // (16, 64)
    dim3 gV   (Vv/128,  BT/128);   // (64, 64)
    dim3 gattn(Tt/128, Bb*Hh);     // (8, 128)

    for (int l = 0; l < Ll; l++) {
        // ln1
        lnorm_k<<<BT, 128>>>(x, ln1_g + l*Cc, ln1_b + l*Cc, h);
        // q,k,v
        sgemm_k<false,false,false><<<g512, 256>>>(h, wq + l*Cc*Cc, nullptr, nullptr, q, BT, Cc, Cc);
        sgemm_k<false,false,false><<<g512, 256>>>(h, wk + l*Cc*Cc, nullptr, nullptr, k, BT, Cc, Cc);
        sgemm_k<false,false,false><<<g512, 256>>>(h, wv + l*Cc*Cc, nullptr, nullptr, v, BT, Cc, Cc);
        // attention
        attn_k<<<gattn, 128>>>(q, k, v, o);
        // x = x + o @ Wo + bo
        sgemm_k<true,false,true><<<g512, 256>>>(o, Wo + (size_t)l*Cc*Cc, bo + l*Cc, x, x, BT, Cc, Cc);
        // ln2
        lnorm_k<<<BT, 128>>>(x, ln2_g + l*Cc, ln2_b + l*Cc, h);
        // ff = relu(h @ W1 + b1)
        sgemm_k<true,true,false><<<g2048, 256>>>(h, W1 + (size_t)l*Cc*FFf, b1 + l*FFf, nullptr, ff, BT, FFf, Cc);
        // x = x + ff @ W2 + b2
        sgemm_k<true,false,true><<<g512, 256>>>(ff, W2 + (size_t)l*FFf*Cc, b2 + l*Cc, x, x, BT, Cc, FFf);
    }
    // final LN
    lnorm_k<<<BT, 128>>>(x, lnf_g, lnf_b, h);
    // logits = h @ Wlm + blm  -> d_out
    sgemm_k<true,false,false><<<gV, 256>>>(h, Wlm, blm, nullptr, out, BT, Vv, Cc);

    // loss
    zero_loss_k<<<1, 1>>>();
    loss_k<<<BT, 256>>>(out, targets);
    int extra = out_size - (int)BTV;
    if (extra > 0) finalize_k<<<1, 128>>>(out, extra);
}

// round 3
// speedup vs baseline: 1.8061x; 1.8061x over previous
#include <cuda_runtime.h>
#include <cuda_fp16.h>
#include <cstdint>
#include <math.h>

// ---------------- problem constants ----------------
#define Vv 8192
#define Cc 512
#define Hh 16
#define HSs 32
#define Ll 12
#define FFf 2048
#define Bb 8
#define Tt 1024
#define BT (Bb*Tt)              // 8192
#define BTV ((size_t)BT * Vv)   // 67108864
#define NQKV 1536

typedef unsigned int u32;

// ---------------- scratch (device globals, no allocation) ----------------
__device__ float g_x  [BT*Cc];
__device__ float g_h  [BT*Cc];
__device__ float g_qkv[BT*NQKV];
__device__ float g_o  [BT*Cc];
__device__ float g_ff [BT*FFf];
__device__ float g_loss;

// split fp16 weights, [N][K] layout per layer
__device__ __half g_wqkv_h[Ll*NQKV*Cc];
__device__ __half g_wqkv_l[Ll*NQKV*Cc];
__device__ __half g_wo_h  [Ll*Cc*Cc];
__device__ __half g_wo_l  [Ll*Cc*Cc];
__device__ __half g_w1_h  [Ll*FFf*Cc];
__device__ __half g_w1_l  [Ll*FFf*Cc];
__device__ __half g_w2_h  [Ll*Cc*FFf];
__device__ __half g_w2_l  [Ll*Cc*FFf];
__device__ __half g_wlm_h [Vv*Cc];
__device__ __half g_wlm_l [Vv*Cc];

// ---------------- mma / ldmatrix wrappers ----------------
__device__ __forceinline__ void mma_f16(float* d, const u32* a, const u32* b) {
    asm volatile("mma.sync.aligned.m16n8k16.row.col.f32.f16.f16.f32 "
        "{%0,%1,%2,%3}, {%4,%5,%6,%7}, {%8,%9}, {%0,%1,%2,%3};"
        : "+f"(d[0]), "+f"(d[1]), "+f"(d[2]), "+f"(d[3])
        : "r"(a[0]), "r"(a[1]), "r"(a[2]), "r"(a[3]),
          "r"(b[0]), "r"(b[1]));
}

__device__ __forceinline__ void ldsm4(u32* r, u32 addr) {
    asm volatile("ldmatrix.sync.aligned.m8n8.x4.shared.b16 "
        "{%0,%1,%2,%3}, [%4];"
        : "=r"(r[0]), "=r"(r[1]), "=r"(r[2]), "=r"(r[3]) : "r"(addr));
}

// ---------------- weight prep: QKV pack + transpose + fp16 split ----------------
// Wq/Wk/Wv [L,H,C,HS] -> qkv weight [L][n=1536][k=512], n = s*512 + h*32 + d
__global__ __launch_bounds__(256) void pack_qkv_split(const float* __restrict__ Wq,
                                                      const float* __restrict__ Wk,
                                                      const float* __restrict__ Wv) {
    __shared__ float t[32][33];
    int l = blockIdx.z, h = blockIdx.y, c0 = blockIdx.x * 32;
    int tx = threadIdx.x, ty = threadIdx.y;
    const float* srcs[3] = {Wq, Wk, Wv};
    for (int s = 0; s < 3; s++) {
        const float* src = srcs[s] + ((size_t)(l*Hh + h) * Cc) * HSs;
        #pragma unroll
        for (int r = 0; r < 4; r++)
            t[ty + 8*r][tx] = src[(size_t)(c0 + ty + 8*r) * HSs + tx];
        __syncthreads();
        size_t nbase = (size_t)l * NQKV + s * 512 + h * 32;
        #pragma unroll
        for (int r = 0; r < 4; r++) {
            int d = ty + 8*r;
            float v = t[tx][d];
            __half hi = __float2half_rn(v);
            __half lo = __float2half_rn(v - __half2float(hi));
            size_t o = (nbase + d) * Cc + c0 + tx;
            g_wqkv_h[o] = hi; g_wqkv_l[o] = lo;
        }
        __syncthreads();
    }
}

// generic [K][N] -> [N][K] transpose + fp16 split; grid (N/32, K/32, layers)
__global__ __launch_bounds__(256) void tsplit_k(const float* __restrict__ src,
                                                __half* __restrict__ hi,
                                                __half* __restrict__ lo,
                                                int K, int N) {
    __shared__ float t[32][33];
    size_t ls = (size_t)blockIdx.z * K * N;
    int n0 = blockIdx.x * 32, k0 = blockIdx.y * 32;
    int tx = threadIdx.x, ty = threadIdx.y;
    #pragma unroll
    for (int r = 0; r < 4; r++)
        t[ty + 8*r][tx] = src[ls + (size_t)(k0 + ty + 8*r) * N + n0 + tx];
    __syncthreads();
    #pragma unroll
    for (int r = 0; r < 4; r++) {
        int n = ty + 8*r;
        float v = t[tx][n];
        __half vh = __float2half_rn(v);
        __half vl = __float2half_rn(v - __half2float(vh));
        size_t o = ls + (size_t)(n0 + n) * K + k0 + tx;
        hi[o] = vh; lo[o] = vl;
    }
}

// ---------------- embedding ----------------
__global__ __launch_bounds__(128) void embed_k(const int* __restrict__ idx,
                                               const int* __restrict__ lab,
                                               const float* __restrict__ tok_emb,
                                               const float* __restrict__ lab_emb,
                                               const float* __restrict__ pos_emb) {
    int i = blockIdx.x;
    int t = i & (Tt-1);
    int ix = idx[i];
    int lb = lab[i];
    const float4* te = (const float4*)(tok_emb + (size_t)ix*Cc);
    const float4* le = (const float4*)(lab_emb + (size_t)lb*Cc);
    const float4* pe = (const float4*)(pos_emb + (size_t)t *Cc);
    float4* xo = (float4*)(g_x + (size_t)i*Cc);
    int c = threadIdx.x;
    float4 a = te[c], b = le[c], p = pe[c];
    xo[c] = make_float4(a.x+b.x+p.x, a.y+b.y+p.y, a.z+b.z+p.z, a.w+b.w+p.w);
}

// ---------------- layernorm ----------------
__global__ __launch_bounds__(128) void lnorm_k(const float* __restrict__ x,
                                               const float* __restrict__ g,
                                               const float* __restrict__ b,
                                               float* __restrict__ y) {
    int row = blockIdx.x;
    const float4* xr = (const float4*)(x + (size_t)row*Cc);
    float4 v = xr[threadIdx.x];
    float s  = v.x+v.y+v.z+v.w;
    float s2 = v.x*v.x + v.y*v.y + v.z*v.z + v.w*v.w;
    for (int o = 16; o > 0; o >>= 1) {
        s  += __shfl_down_sync(0xffffffff, s,  o);
        s2 += __shfl_down_sync(0xffffffff, s2, o);
    }
    __shared__ float sh[4], sh2[4];
    int wid = threadIdx.x >> 5, lane = threadIdx.x & 31;
    if (lane == 0) { sh[wid] = s; sh2[wid] = s2; }
    __syncthreads();
    __shared__ float smean, srstd;
    if (threadIdx.x == 0) {
        float ts = sh[0]+sh[1]+sh[2]+sh[3];
        float ts2 = sh2[0]+sh2[1]+sh2[2]+sh2[3];
        float mean = ts * (1.0f/Cc);
        float var = ts2 * (1.0f/Cc) - mean*mean;
        smean = mean;
        srstd = rsqrtf(var + 1e-5f);
    }
    __syncthreads();
    float mean = smean, rstd = srstd;
    int c = threadIdx.x * 4;
    float4 gg = *(const float4*)(g + c);
    float4 bb = *(const float4*)(b + c);
    float4 out;
    out.x = (v.x-mean)*rstd*gg.x + bb.x;
    out.y = (v.y-mean)*rstd*gg.y + bb.y;
    out.z = (v.z-mean)*rstd*gg.z + bb.z;
    out.w = (v.w-mean)*rstd*gg.w + bb.w;
    ((float4*)(y + (size_t)row*Cc))[threadIdx.x] = out;
}

// ---------------- tensor-core GEMM (fp16x3 split, fp32 accum) ----------------
// C[M,N] = [res +] A[M,K] @ B[N,K]^T(stored [N][K]) [+bias] [relu]
// block tile 128x128x32, 8 warps (2x4), warp tile 64x32, mma m16n8k16
// smem halves layout: Ah[128][40] @0, Al @5120, Bh @10240, Bl @15360 (20480 halves = 40KB)
#define SA_H 0
#define SA_L 5120
#define SB_H 10240
#define SB_L 15360

template<bool BIAS, bool RELU, bool RES>
__global__ __launch_bounds__(256) void hgemm_k(const float* __restrict__ A,
                                               const __half* __restrict__ Bhg,
                                               const __half* __restrict__ Blg,
                                               const float* __restrict__ bias,
                                               const float* __restrict__ res,
                                               float* __restrict__ Cm,
                                               int M, int N, int K) {
    __shared__ __half sm[20480];
    const int tid = threadIdx.x;
    const int lane = tid & 31, w = tid >> 5;
    const int row0 = blockIdx.y * 128, col0 = blockIdx.x * 128;
    const int m0w = (w >> 2) * 64, n0w = (w & 3) * 32;

    float acc[4][4][4];
    #pragma unroll
    for (int i = 0; i < 4; i++)
        #pragma unroll
        for (int j = 0; j < 4; j++)
            #pragma unroll
            for (int e = 0; e < 4; e++) acc[i][j][e] = 0.f;

    // gmem load indices
    const int am = tid >> 3;            // + 32*i
    const int ak4 = (tid & 7) * 4;
    const int bn = tid >> 2;            // + 64*i
    const int bk8 = (tid & 3) * 8;

    const u32 sb = (u32)__cvta_generic_to_shared(sm);

    float4 aR[4];
    uint4 bhR[2], blR[2];

    const int nk = K >> 5;

    // preload tile 0
    #pragma unroll
    for (int i = 0; i < 4; i++)
        aR[i] = *(const float4*)(A + (size_t)(row0 + am + 32*i) * K + ak4);
    #pragma unroll
    for (int i = 0; i < 2; i++) {
        size_t gb = (size_t)(col0 + bn + 64*i) * K + bk8;
        bhR[i] = *(const uint4*)(Bhg + gb);
        blR[i] = *(const uint4*)(Blg + gb);
    }

    // ldmatrix per-lane coordinates
    const int lr = lane & 7, lg1 = (lane >> 3) & 1, lg2 = lane >> 4;

    for (int kt = 0; kt < nk; kt++) {
        // store staged regs -> smem (convert A to hi/lo fp16)
        #pragma unroll
        for (int i = 0; i < 4; i++) {
            __half h4[4], l4[4];
            float vv[4] = {aR[i].x, aR[i].y, aR[i].z, aR[i].w};
            #pragma unroll
            for (int e = 0; e < 4; e++) {
                h4[e] = __float2half_rn(vv[e]);
                l4[e] = __float2half_rn(vv[e] - __half2float(h4[e]));
            }
            int off = (am + 32*i) * 40 + ak4;
            *(uint2*)(sm + SA_H + off) = *(uint2*)h4;
            *(uint2*)(sm + SA_L + off) = *(uint2*)l4;
        }
        #pragma unroll
        for (int i = 0; i < 2; i++) {
            int off = (bn + 64*i) * 40 + bk8;
            *(uint4*)(sm + SB_H + off) = bhR[i];
            *(uint4*)(sm + SB_L + off) = blR[i];
        }
        __syncthreads();

        // prefetch next tile
        if (kt + 1 < nk) {
            int k0g = (kt + 1) << 5;
            #pragma unroll
            for (int i = 0; i < 4; i++)
                aR[i] = *(const float4*)(A + (size_t)(row0 + am + 32*i) * K + k0g + ak4);
            #pragma unroll
            for (int i = 0; i < 2; i++) {
                size_t gb = (size_t)(col0 + bn + 64*i) * K + k0g + bk8;
                bhR[i] = *(const uint4*)(Bhg + gb);
                blR[i] = *(const uint4*)(Blg + gb);
            }
        }

        // compute 2 k16 steps
        #pragma unroll
        for (int ks = 0; ks < 32; ks += 16) {
            u32 afh[4][4], afl[4][4];
            #pragma unroll
            for (int mi = 0; mi < 4; mi++) {
                int row = m0w + mi*16 + lr + lg1*8;
                int kk = ks + lg2*8;
                u32 ad = sb + (u32)(row*40 + kk) * 2;
                ldsm4(afh[mi], ad);
                ldsm4(afl[mi], ad + SA_L*2);
            }
            u32 bfh[4][2], bfl[4][2];
            #pragma unroll
            for (int bi = 0; bi < 2; bi++) {
                int n = n0w + bi*16 + lr + lg2*8;
                int kk = ks + lg1*8;
                u32 bd = sb + (u32)(SB_H + n*40 + kk) * 2;
                u32 t1[4], t2[4];
                ldsm4(t1, bd);
                ldsm4(t2, bd + 5120*2);
                bfh[2*bi][0]   = t1[0]; bfh[2*bi][1]   = t1[1];
                bfh[2*bi+1][0] = t1[2]; bfh[2*bi+1][1] = t1[3];
                bfl[2*bi][0]   = t2[0]; bfl[2*bi][1]   = t2[1];
                bfl[2*bi+1][0] = t2[2]; bfl[2*bi+1][1] = t2[3];
            }
            #pragma unroll
            for (int mi = 0; mi < 4; mi++)
                #pragma unroll
                for (int ni = 0; ni < 4; ni++) {
                    mma_f16(acc[mi][ni], afh[mi], bfh[ni]);
                    mma_f16(acc[mi][ni], afh[mi], bfl[ni]);
                    mma_f16(acc[mi][ni], afl[mi], bfh[ni]);
                }
        }
        __syncthreads();
    }

    // epilogue
    #pragma unroll
    for (int mi = 0; mi < 4; mi++) {
        int r0 = row0 + m0w + mi*16 + (lane >> 2);
        #pragma unroll
        for (int ni = 0; ni < 4; ni++) {
            int cc = col0 + n0w + ni*8 + (lane & 3)*2;
            float2 v0 = make_float2(acc[mi][ni][0], acc[mi][ni][1]);
            float2 v1 = make_float2(acc[mi][ni][2], acc[mi][ni][3]);
            if (BIAS) {
                float2 bb = *(const float2*)(bias + cc);
                v0.x += bb.x; v0.y += bb.y; v1.x += bb.x; v1.y += bb.y;
            }
            if (RELU) {
                v0.x = fmaxf(v0.x, 0.f); v0.y = fmaxf(v0.y, 0.f);
                v1.x = fmaxf(v1.x, 0.f); v1.y = fmaxf(v1.y, 0.f);
            }
            if (RES) {
                float2 ra = *(const float2*)(res + (size_t)r0*N + cc);
                float2 rb = *(const float2*)(res + (size_t)(r0+8)*N + cc);
                v0.x += ra.x; v0.y += ra.y; v1.x += rb.x; v1.y += rb.y;
            }
            *(float2*)(Cm + (size_t)r0*N + cc) = v0;
            *(float2*)(Cm + (size_t)(r0+8)*N + cc) = v1;
        }
    }
}

// ---------------- causal flash attention (1 thread = 1 query row) ----------------
__global__ __launch_bounds__(128) void attn_k(const float* __restrict__ qkv,
                                              float* __restrict__ o) {
    __shared__ float Ksh[64][HSs];
    __shared__ float Vsh[64][HSs];
    int bh = blockIdx.y;
    int b = bh >> 4, h = bh & 15;
    int qi = blockIdx.x * 128 + threadIdx.x;
    const float scale = 0.17677669529663689f;

    float qr[HSs];
    {
        const float4* qp = (const float4*)(qkv + (size_t)(b*Tt + qi)*NQKV + h*HSs);
        #pragma unroll
        for (int i = 0; i < 8; i++) *(float4*)&qr[i*4] = qp[i];
    }
    float m = -1e30f, ssum = 0.f;
    float acc[HSs];
    #pragma unroll
    for (int d = 0; d < HSs; d++) acc[d] = 0.f;

    int ntiles = (blockIdx.x + 1) * 2;
    for (int kt = 0; kt < ntiles; kt++) {
        int kbase = kt * 64;
        #pragma unroll
        for (int i = 0; i < 4; i++) {
            int f = threadIdx.x + i * 128;
            int r = f >> 3, d4 = (f & 7) << 2;
            size_t gi = (size_t)(b*Tt + kbase + r)*NQKV + h*HSs + d4;
            *(float4*)&Ksh[r][d4] = *(const float4*)(qkv + gi + 512);
            *(float4*)&Vsh[r][d4] = *(const float4*)(qkv + gi + 1024);
        }
        __syncthreads();

        float sj[64];
        float tm = -1e30f;
        #pragma unroll
        for (int j = 0; j < 64; j++) {
            float s = -1e30f;
            if (kbase + j <= qi) {
                float dsum = 0.f;
                #pragma unroll
                for (int d = 0; d < HSs; d++) dsum = fmaf(qr[d], Ksh[j][d], dsum);
                s = dsum * scale;
                tm = fmaxf(tm, s);
            }
            sj[j] = s;
        }
        if (tm > -1e29f) {
            float mn = fmaxf(m, tm);
            float corr = __expf(m - mn);
            ssum *= corr;
            #pragma unroll
            for (int d = 0; d < HSs; d++) acc[d] *= corr;
            #pragma unroll
            for (int j = 0; j < 64; j++) {
                float p = __expf(sj[j] - mn);
                ssum += p;
                #pragma unroll
                for (int d = 0; d < HSs; d++) acc[d] = fmaf(p, Vsh[j][d], acc[d]);
            }
            m = mn;
        }
        __syncthreads();
    }
    float inv = 1.f / ssum;
    float* op = o + (size_t)(b*Tt + qi)*Cc + h*HSs;
    #pragma unroll
    for (int i = 0; i < 8; i++) {
        float4 wv;
        wv.x = acc[i*4+0]*inv; wv.y = acc[i*4+1]*inv;
        wv.z = acc[i*4+2]*inv; wv.w = acc[i*4+3]*inv;
        *(float4*)(op + i*4) = wv;
    }
}

// ---------------- loss ----------------
__global__ void zero_loss_k() { g_loss = 0.f; }

__global__ __launch_bounds__(256) void loss_k(const float* __restrict__ logits,
                                              const int* __restrict__ targets) {
    int row = blockIdx.x;
    const float* lr = logits + (size_t)row * Vv;
    float mx = -1e30f;
    for (int i = threadIdx.x; i < Vv; i += 256) mx = fmaxf(mx, lr[i]);
    for (int o = 16; o > 0; o >>= 1) mx = fmaxf(mx, __shfl_down_sync(0xffffffff, mx, o));
    __shared__ float shm[8];
    int wid = threadIdx.x >> 5, lane = threadIdx.x & 31;
    if (lane == 0) shm[wid] = mx;
    __syncthreads();
    __shared__ float rowmax;
    if (threadIdx.x == 0) {
        float t = shm[0];
        for (int i = 1; i < 8; i++) t = fmaxf(t, shm[i]);
        rowmax = t;
    }
    __syncthreads();
    float rm = rowmax;
    float se = 0.f;
    for (int i = threadIdx.x; i < Vv; i += 256) se += __expf(lr[i] - rm);
    for (int o = 16; o > 0; o >>= 1) se += __shfl_down_sync(0xffffffff, se, o);
    if (lane == 0) shm[wid] = se;
    __syncthreads();
    if (threadIdx.x == 0) {
        float t = 0.f;
        for (int i = 0; i < 8; i++) t += shm[i];
        float lp = lr[targets[row]] - rm - logf(t);
        atomicAdd(&g_loss, lp);
    }
}

__global__ void finalize_k(float* out, int extra) {
    float lv = -g_loss / (float)BT;
    for (int i = threadIdx.x + blockIdx.x*blockDim.x; i < extra; i += blockDim.x*gridDim.x)
        out[BTV + i] = lv;
}

// ---------------- host launcher ----------------
static void* symaddr(const void* sym) {
    void* p = nullptr;
    cudaGetSymbolAddress(&p, sym);
    return p;
}

extern "C" void kernel_launch(void* const* d_in, const int* in_sizes, int n_in,
                              void* d_out, int out_size) {
    const int*   idx      = (const int*)  d_in[0];
    const int*   idx_lab  = (const int*)  d_in[1];
    const int*   targets  = (const int*)  d_in[2];
    const float* tok_emb  = (const float*)d_in[3];
    const float* pos_emb  = (const float*)d_in[4];
    const float* lab_emb  = (const float*)d_in[5];
    const float* Wq       = (const float*)d_in[6];
    const float* Wk       = (const float*)d_in[7];
    const float* Wv       = (const float*)d_in[8];
    const float* Wo       = (const float*)d_in[9];
    const float* bo       = (const float*)d_in[10];
    const float* ln1_g    = (const float*)d_in[11];
    const float* ln1_b    = (const float*)d_in[12];
    const float* W1       = (const float*)d_in[13];
    const float* b1       = (const float*)d_in[14];
    const float* W2       = (const float*)d_in[15];
    const float* b2       = (const float*)d_in[16];
    const float* ln2_g    = (const float*)d_in[17];
    const float* ln2_b    = (const float*)d_in[18];
    const float* lnf_g    = (const float*)d_in[19];
    const float* lnf_b    = (const float*)d_in[20];
    const float* Wlm      = (const float*)d_in[21];
    const float* blm      = (const float*)d_in[22];
    float* out = (float*)d_out;

    float* x   = (float*)symaddr(g_x);
    float* h   = (float*)symaddr(g_h);
    float* qkv = (float*)symaddr(g_qkv);
    float* o   = (float*)symaddr(g_o);
    float* ff  = (float*)symaddr(g_ff);
    __half* wqkv_h = (__half*)symaddr(g_wqkv_h);
    __half* wqkv_l = (__half*)symaddr(g_wqkv_l);
    __half* wo_h   = (__half*)symaddr(g_wo_h);
    __half* wo_l   = (__half*)symaddr(g_wo_l);
    __half* w1_h   = (__half*)symaddr(g_w1_h);
    __half* w1_l   = (__half*)symaddr(g_w1_l);
    __half* w2_h   = (__half*)symaddr(g_w2_h);
    __half* w2_l   = (__half*)symaddr(g_w2_l);
    __half* wlm_h  = (__half*)symaddr(g_wlm_h);
    __half* wlm_l  = (__half*)symaddr(g_wlm_l);

    dim3 tb(32, 8);
    // weight prep (runs per launch; small vs GEMM cost)
    pack_qkv_split<<<dim3(16, 16, 12), tb>>>(Wq, Wk, Wv);
    tsplit_k<<<dim3(16, 16, 12), tb>>>(Wo,  wo_h,  wo_l,  Cc,  Cc);
    tsplit_k<<<dim3(64, 16, 12), tb>>>(W1,  w1_h,  w1_l,  Cc,  FFf);
    tsplit_k<<<dim3(16, 64, 12), tb>>>(W2,  w2_h,  w2_l,  FFf, Cc);
    tsplit_k<<<dim3(256, 16, 1), tb>>>(Wlm, wlm_h, wlm_l, Cc,  Vv);

    // embedding
    embed_k<<<BT, 128>>>(idx, idx_lab, tok_emb, lab_emb, pos_emb);

    dim3 gQKV(NQKV/128, BT/128);   // (12, 64)
    dim3 g512(Cc/128,   BT/128);   // (4, 64)
    dim3 g2048(FFf/128, BT/128);   // (16, 64)
    dim3 gV(Vv/128,     BT/128);   // (64, 64)
    dim3 gattn(Tt/128, Bb*Hh);     // (8, 128)

    for (int l = 0; l < Ll; l++) {
        lnorm_k<<<BT, 128>>>(x, ln1_g + l*Cc, ln1_b + l*Cc, h);
        // fused qkv: [BT,1536]
        hgemm_k<false,false,false><<<gQKV, 256>>>(h, wqkv_h + (size_t)l*NQKV*Cc,
                                                  wqkv_l + (size_t)l*NQKV*Cc,
                                                  nullptr, nullptr, qkv, BT, NQKV, Cc);
        attn_k<<<gattn, 128>>>(qkv, o);
        // x = x + o @ Wo + bo
        hgemm_k<true,false,true><<<g512, 256>>>(o, wo_h + (size_t)l*Cc*Cc,
                                                wo_l + (size_t)l*Cc*Cc,
                                                bo + l*Cc, x, x, BT, Cc, Cc);
        lnorm_k<<<BT, 128>>>(x, ln2_g + l*Cc, ln2_b + l*Cc, h);
        // ff = relu(h @ W1 + b1)
        hgemm_k<true,true,false><<<g2048, 256>>>(h, w1_h + (size_t)l*FFf*Cc,
                                                 w1_l + (size_t)l*FFf*Cc,
                                                 b1 + l*FFf, nullptr, ff, BT, FFf, Cc);
        // x = x + ff @ W2 + b2
        hgemm_k<true,false,true><<<g512, 256>>>(ff, w2_h + (size_t)l*Cc*FFf,
                                                w2_l + (size_t)l*Cc*FFf,
                                                b2 + l*Cc, x, x, BT, Cc, FFf);
    }
    lnorm_k<<<BT, 128>>>(x, lnf_g, lnf_b, h);
    // logits
    hgemm_k<true,false,false><<<gV, 256>>>(h, wlm_h, wlm_l, blm, nullptr, out, BT, Vv, Cc);

    // loss
    zero_loss_k<<<1, 1>>>();
    loss_k<<<BT, 256>>>(out, targets);
    int extra = out_size - (int)BTV;
    if (extra > 0) finalize_k<<<1, 128>>>(out, extra);
}

// round 4
// speedup vs baseline: 2.0399x; 1.1295x over previous
#include <cuda_runtime.h>
#include <cuda_fp16.h>
#include <cstdint>
#include <math.h>

// ---------------- problem constants ----------------
#define Vv 8192
#define Cc 512
#define Hh 16
#define HSs 32
#define Ll 12
#define FFf 2048
#define Bb 8
#define Tt 1024
#define BT (Bb*Tt)              // 8192
#define BTV ((size_t)BT * Vv)   // 67108864
#define NQKV 1536

typedef unsigned int u32;
typedef unsigned long long u64;

// ---------------- scratch (device globals, no allocation) ----------------
__device__ float g_x  [BT*Cc];
__device__ float g_h  [BT*Cc];
__device__ float g_qkv[BT*NQKV];
__device__ float g_o  [BT*Cc];
__device__ float g_ff [BT*FFf];
__device__ float g_loss;

// split fp16 weights, [N][K] layout per layer
__device__ __half g_wqkv_h[Ll*NQKV*Cc];
__device__ __half g_wqkv_l[Ll*NQKV*Cc];
__device__ __half g_wo_h  [Ll*Cc*Cc];
__device__ __half g_wo_l  [Ll*Cc*Cc];
__device__ __half g_w1_h  [Ll*FFf*Cc];
__device__ __half g_w1_l  [Ll*FFf*Cc];
__device__ __half g_w2_h  [Ll*Cc*FFf];
__device__ __half g_w2_l  [Ll*Cc*FFf];
__device__ __half g_wlm_h [Vv*Cc];
__device__ __half g_wlm_l [Vv*Cc];

// ---------------- mma / ldmatrix / f32x2 wrappers ----------------
__device__ __forceinline__ void mma_f16(float* d, const u32* a, const u32* b) {
    asm volatile("mma.sync.aligned.m16n8k16.row.col.f32.f16.f16.f32 "
        "{%0,%1,%2,%3}, {%4,%5,%6,%7}, {%8,%9}, {%0,%1,%2,%3};"
        : "+f"(d[0]), "+f"(d[1]), "+f"(d[2]), "+f"(d[3])
        : "r"(a[0]), "r"(a[1]), "r"(a[2]), "r"(a[3]),
          "r"(b[0]), "r"(b[1]));
}

__device__ __forceinline__ void ldsm4(u32* r, u32 addr) {
    asm volatile("ldmatrix.sync.aligned.m8n8.x4.shared.b16 "
        "{%0,%1,%2,%3}, [%4];"
        : "=r"(r[0]), "=r"(r[1]), "=r"(r[2]), "=r"(r[3]) : "r"(addr));
}

__device__ __forceinline__ void fma2(u64 &d, u64 a, u64 b) {
    asm("fma.rn.f32x2 %0, %1, %2, %0;" : "+l"(d) : "l"(a), "l"(b));
}
__device__ __forceinline__ void mul2(u64 &d, u64 a) {
    asm("mul.rn.f32x2 %0, %0, %1;" : "+l"(d) : "l"(a));
}
__device__ __forceinline__ u64 pack2(float x, float y) {
    u64 r; asm("mov.b64 %0, {%1,%2};" : "=l"(r) : "f"(x), "f"(y)); return r;
}
__device__ __forceinline__ float2 unpack2(u64 v) {
    float2 f; asm("mov.b64 {%0,%1}, %2;" : "=f"(f.x), "=f"(f.y) : "l"(v)); return f;
}

// ---------------- weight prep: QKV pack + transpose + fp16 split ----------------
__global__ __launch_bounds__(256) void pack_qkv_split(const float* __restrict__ Wq,
                                                      const float* __restrict__ Wk,
                                                      const float* __restrict__ Wv) {
    __shared__ float t[32][33];
    int l = blockIdx.z, h = blockIdx.y, c0 = blockIdx.x * 32;
    int tx = threadIdx.x, ty = threadIdx.y;
    const float* srcs[3] = {Wq, Wk, Wv};
    for (int s = 0; s < 3; s++) {
        const float* src = srcs[s] + ((size_t)(l*Hh + h) * Cc) * HSs;
        #pragma unroll
        for (int r = 0; r < 4; r++)
            t[ty + 8*r][tx] = src[(size_t)(c0 + ty + 8*r) * HSs + tx];
        __syncthreads();
        size_t nbase = (size_t)l * NQKV + s * 512 + h * 32;
        #pragma unroll
        for (int r = 0; r < 4; r++) {
            int d = ty + 8*r;
            float v = t[tx][d];
            __half hi = __float2half_rn(v);
            __half lo = __float2half_rn(v - __half2float(hi));
            size_t o = (nbase + d) * Cc + c0 + tx;
            g_wqkv_h[o] = hi; g_wqkv_l[o] = lo;
        }
        __syncthreads();
    }
}

__global__ __launch_bounds__(256) void tsplit_k(const float* __restrict__ src,
                                                __half* __restrict__ hi,
                                                __half* __restrict__ lo,
                                                int K, int N) {
    __shared__ float t[32][33];
    size_t ls = (size_t)blockIdx.z * K * N;
    int n0 = blockIdx.x * 32, k0 = blockIdx.y * 32;
    int tx = threadIdx.x, ty = threadIdx.y;
    #pragma unroll
    for (int r = 0; r < 4; r++)
        t[ty + 8*r][tx] = src[ls + (size_t)(k0 + ty + 8*r) * N + n0 + tx];
    __syncthreads();
    #pragma unroll
    for (int r = 0; r < 4; r++) {
        int n = ty + 8*r;
        float v = t[tx][n];
        __half vh = __float2half_rn(v);
        __half vl = __float2half_rn(v - __half2float(vh));
        size_t o = ls + (size_t)(n0 + n) * K + k0 + tx;
        hi[o] = vh; lo[o] = vl;
    }
}

// ---------------- embedding ----------------
__global__ __launch_bounds__(128) void embed_k(const int* __restrict__ idx,
                                               const int* __restrict__ lab,
                                               const float* __restrict__ tok_emb,
                                               const float* __restrict__ lab_emb,
                                               const float* __restrict__ pos_emb) {
    int i = blockIdx.x;
    int t = i & (Tt-1);
    int ix = idx[i];
    int lb = lab[i];
    const float4* te = (const float4*)(tok_emb + (size_t)ix*Cc);
    const float4* le = (const float4*)(lab_emb + (size_t)lb*Cc);
    const float4* pe = (const float4*)(pos_emb + (size_t)t *Cc);
    float4* xo = (float4*)(g_x + (size_t)i*Cc);
    int c = threadIdx.x;
    float4 a = te[c], b = le[c], p = pe[c];
    xo[c] = make_float4(a.x+b.x+p.x, a.y+b.y+p.y, a.z+b.z+p.z, a.w+b.w+p.w);
}

// ---------------- layernorm ----------------
__global__ __launch_bounds__(128) void lnorm_k(const float* __restrict__ x,
                                               const float* __restrict__ g,
                                               const float* __restrict__ b,
                                               float* __restrict__ y) {
    int row = blockIdx.x;
    const float4* xr = (const float4*)(x + (size_t)row*Cc);
    float4 v = xr[threadIdx.x];
    float s  = v.x+v.y+v.z+v.w;
    float s2 = v.x*v.x + v.y*v.y + v.z*v.z + v.w*v.w;
    for (int o = 16; o > 0; o >>= 1) {
        s  += __shfl_down_sync(0xffffffff, s,  o);
        s2 += __shfl_down_sync(0xffffffff, s2, o);
    }
    __shared__ float sh[4], sh2[4];
    int wid = threadIdx.x >> 5, lane = threadIdx.x & 31;
    if (lane == 0) { sh[wid] = s; sh2[wid] = s2; }
    __syncthreads();
    __shared__ float smean, srstd;
    if (threadIdx.x == 0) {
        float ts = sh[0]+sh[1]+sh[2]+sh[3];
        float ts2 = sh2[0]+sh2[1]+sh2[2]+sh2[3];
        float mean = ts * (1.0f/Cc);
        float var = ts2 * (1.0f/Cc) - mean*mean;
        smean = mean;
        srstd = rsqrtf(var + 1e-5f);
    }
    __syncthreads();
    float mean = smean, rstd = srstd;
    int c = threadIdx.x * 4;
    float4 gg = *(const float4*)(g + c);
    float4 bb = *(const float4*)(b + c);
    float4 out;
    out.x = (v.x-mean)*rstd*gg.x + bb.x;
    out.y = (v.y-mean)*rstd*gg.y + bb.y;
    out.z = (v.z-mean)*rstd*gg.z + bb.z;
    out.w = (v.w-mean)*rstd*gg.w + bb.w;
    ((float4*)(y + (size_t)row*Cc))[threadIdx.x] = out;
}

// ---------------- tensor-core GEMM (fp16x3 split, fp32 accum) ----------------
// C[M,N] = [res +] A[M,K] @ B[N,K]^T(stored [N][K]) [+bias] [relu]
// block tile 128x128x32, 8 warps (2x4), warp tile 64x32, mma m16n8k16
// dynamic smem: 2 buffers x 20480 halves (40KB) = 80KB
#define SA_H 0
#define SA_L 5120
#define SB_H 10240
#define SB_L 15360
#define BUFH 20480

template<bool BIAS, bool RELU, bool RES>
__global__ __launch_bounds__(256) void hgemm_k(const float* __restrict__ A,
                                               const __half* __restrict__ Bhg,
                                               const __half* __restrict__ Blg,
                                               const float* __restrict__ bias,
                                               const float* __restrict__ res,
                                               float* __restrict__ Cm,
                                               int M, int N, int K) {
    extern __shared__ __half smd[];
    const int tid = threadIdx.x;
    const int lane = tid & 31, w = tid >> 5;
    const int row0 = blockIdx.y * 128, col0 = blockIdx.x * 128;
    const int m0w = (w >> 2) * 64, n0w = (w & 3) * 32;

    float acc[4][4][4];
    #pragma unroll
    for (int i = 0; i < 4; i++)
        #pragma unroll
        for (int j = 0; j < 4; j++)
            #pragma unroll
            for (int e = 0; e < 4; e++) acc[i][j][e] = 0.f;

    const int am = tid >> 3;            // + 32*i
    const int ak4 = (tid & 7) * 4;
    const int bn = tid >> 2;            // + 64*i
    const int bk8 = (tid & 3) * 8;

    const u32 sb = (u32)__cvta_generic_to_shared(smd);

    float4 aR[4];
    uint4 bhR[2], blR[2];

    const int nk = K >> 5;

    // preload tile 0
    #pragma unroll
    for (int i = 0; i < 4; i++)
        aR[i] = *(const float4*)(A + (size_t)(row0 + am + 32*i) * K + ak4);
    #pragma unroll
    for (int i = 0; i < 2; i++) {
        size_t gb = (size_t)(col0 + bn + 64*i) * K + bk8;
        bhR[i] = *(const uint4*)(Bhg + gb);
        blR[i] = *(const uint4*)(Blg + gb);
    }
    // store tile 0 -> buffer 0
    #pragma unroll
    for (int i = 0; i < 4; i++) {
        __half h4[4], l4[4];
        float vv[4] = {aR[i].x, aR[i].y, aR[i].z, aR[i].w};
        #pragma unroll
        for (int e = 0; e < 4; e++) {
            h4[e] = __float2half_rn(vv[e]);
            l4[e] = __float2half_rn(vv[e] - __half2float(h4[e]));
        }
        int off = (am + 32*i) * 40 + ak4;
        *(uint2*)(smd + SA_H + off) = *(uint2*)h4;
        *(uint2*)(smd + SA_L + off) = *(uint2*)l4;
    }
    #pragma unroll
    for (int i = 0; i < 2; i++) {
        int off = (bn + 64*i) * 40 + bk8;
        *(uint4*)(smd + SB_H + off) = bhR[i];
        *(uint4*)(smd + SB_L + off) = blR[i];
    }
    __syncthreads();

    const int lr = lane & 7, lg1 = (lane >> 3) & 1, lg2 = lane >> 4;

    for (int kt = 0; kt < nk; kt++) {
        const int cur = (kt & 1) * BUFH;
        const int nxt = ((kt + 1) & 1) * BUFH;
        const bool more = (kt + 1 < nk);

        // prefetch next tile gmem -> regs
        if (more) {
            int k0g = (kt + 1) << 5;
            #pragma unroll
            for (int i = 0; i < 4; i++)
                aR[i] = *(const float4*)(A + (size_t)(row0 + am + 32*i) * K + k0g + ak4);
            #pragma unroll
            for (int i = 0; i < 2; i++) {
                size_t gb = (size_t)(col0 + bn + 64*i) * K + k0g + bk8;
                bhR[i] = *(const uint4*)(Bhg + gb);
                blR[i] = *(const uint4*)(Blg + gb);
            }
        }

        // compute from cur
        #pragma unroll
        for (int ks = 0; ks < 32; ks += 16) {
            u32 afh[4][4], afl[4][4];
            #pragma unroll
            for (int mi = 0; mi < 4; mi++) {
                int row = m0w + mi*16 + lr + lg1*8;
                int kk = ks + lg2*8;
                u32 ad = sb + (u32)(cur + row*40 + kk) * 2;
                ldsm4(afh[mi], ad);
                ldsm4(afl[mi], ad + SA_L*2);
            }
            u32 bfh[4][2], bfl[4][2];
            #pragma unroll
            for (int bi = 0; bi < 2; bi++) {
                int n = n0w + bi*16 + lr + lg2*8;
                int kk = ks + lg1*8;
                u32 bd = sb + (u32)(cur + SB_H + n*40 + kk) * 2;
                u32 t1[4], t2[4];
                ldsm4(t1, bd);
                ldsm4(t2, bd + 5120*2);
                bfh[2*bi][0]   = t1[0]; bfh[2*bi][1]   = t1[1];
                bfh[2*bi+1][0] = t1[2]; bfh[2*bi+1][1] = t1[3];
                bfl[2*bi][0]   = t2[0]; bfl[2*bi][1]   = t2[1];
                bfl[2*bi+1][0] = t2[2]; bfl[2*bi+1][1] = t2[3];
            }
            #pragma unroll
            for (int mi = 0; mi < 4; mi++)
                #pragma unroll
                for (int ni = 0; ni < 4; ni++) {
                    mma_f16(acc[mi][ni], afh[mi], bfh[ni]);
                    mma_f16(acc[mi][ni], afh[mi], bfl[ni]);
                    mma_f16(acc[mi][ni], afl[mi], bfh[ni]);
                }
        }

        // store next tile regs -> nxt buffer
        if (more) {
            #pragma unroll
            for (int i = 0; i < 4; i++) {
                __half h4[4], l4[4];
                float vv[4] = {aR[i].x, aR[i].y, aR[i].z, aR[i].w};
                #pragma unroll
                for (int e = 0; e < 4; e++) {
                    h4[e] = __float2half_rn(vv[e]);
                    l4[e] = __float2half_rn(vv[e] - __half2float(h4[e]));
                }
                int off = nxt + (am + 32*i) * 40 + ak4;
                *(uint2*)(smd + SA_H + off) = *(uint2*)h4;
                *(uint2*)(smd + SA_L + off) = *(uint2*)l4;
            }
            #pragma unroll
            for (int i = 0; i < 2; i++) {
                int off = nxt + (bn + 64*i) * 40 + bk8;
                *(uint4*)(smd + SB_H + off) = bhR[i];
                *(uint4*)(smd + SB_L + off) = blR[i];
            }
        }
        __syncthreads();
    }

    // epilogue
    #pragma unroll
    for (int mi = 0; mi < 4; mi++) {
        int r0 = row0 + m0w + mi*16 + (lane >> 2);
        #pragma unroll
        for (int ni = 0; ni < 4; ni++) {
            int cc = col0 + n0w + ni*8 + (lane & 3)*2;
            float2 v0 = make_float2(acc[mi][ni][0], acc[mi][ni][1]);
            float2 v1 = make_float2(acc[mi][ni][2], acc[mi][ni][3]);
            if (BIAS) {
                float2 bb = *(const float2*)(bias + cc);
                v0.x += bb.x; v0.y += bb.y; v1.x += bb.x; v1.y += bb.y;
            }
            if (RELU) {
                v0.x = fmaxf(v0.x, 0.f); v0.y = fmaxf(v0.y, 0.f);
                v1.x = fmaxf(v1.x, 0.f); v1.y = fmaxf(v1.y, 0.f);
            }
            if (RES) {
                float2 ra = *(const float2*)(res + (size_t)r0*N + cc);
                float2 rb = *(const float2*)(res + (size_t)(r0+8)*N + cc);
                v0.x += ra.x; v0.y += ra.y; v1.x += rb.x; v1.y += rb.y;
            }
            *(float2*)(Cm + (size_t)r0*N + cc) = v0;
            *(float2*)(Cm + (size_t)(r0+8)*N + cc) = v1;
        }
    }
}

// ---------------- causal flash attention (f32x2 packed, online softmax) ----------------
__global__ __launch_bounds__(128) void attn_k(const float* __restrict__ qkv,
                                              float* __restrict__ o) {
    __shared__ float Ksh[64][HSs];
    __shared__ float Vsh[64][HSs];
    int bh = blockIdx.y;
    int b = bh >> 4, h = bh & 15;
    int qt = gridDim.x - 1 - blockIdx.x;       // heaviest tiles first
    int qi = qt * 128 + threadIdx.x;
    const float scale = 0.17677669529663689f;

    u64 qp[16];
    {
        const float* qpf = qkv + (size_t)(b*Tt + qi)*NQKV + h*HSs;
        #pragma unroll
        for (int p = 0; p < 8; p++) {
            ulonglong2 t = *(const ulonglong2*)(qpf + p*4);
            qp[2*p] = t.x; qp[2*p+1] = t.y;
        }
    }
    float m = -1e30f, ssum = 0.f;
    u64 accp[16];
    #pragma unroll
    for (int d = 0; d < 16; d++) accp[d] = 0ull;

    int ntiles = (qt + 1) * 2;
    for (int kt = 0; kt < ntiles; kt++) {
        int kbase = kt * 64;
        #pragma unroll
        for (int i = 0; i < 4; i++) {
            int f = threadIdx.x + i * 128;
            int r = f >> 3, d4 = (f & 7) << 2;
            size_t gi = (size_t)(b*Tt + kbase + r)*NQKV + h*HSs + d4;
            *(float4*)&Ksh[r][d4] = *(const float4*)(qkv + gi + 512);
            *(float4*)&Vsh[r][d4] = *(const float4*)(qkv + gi + 1024);
        }
        __syncthreads();

        int rel = qi - kbase + 1;
        int jmax = rel < 64 ? (rel < 0 ? 0 : rel) : 64;
        for (int j = 0; j < jmax; j++) {
            // dot(q, K[j]) with packed f32x2
            u64 dp0 = 0ull, dp1 = 0ull;
            #pragma unroll
            for (int p = 0; p < 8; p++) {
                ulonglong2 kk = *(const ulonglong2*)&Ksh[j][p*4];
                fma2(dp0, qp[2*p],   kk.x);
                fma2(dp1, qp[2*p+1], kk.y);
            }
            float2 a0 = unpack2(dp0), a1 = unpack2(dp1);
            float s = (a0.x + a0.y + a1.x + a1.y) * scale;

            float p;
            if (s <= m) {
                p = __expf(s - m);
            } else {
                float corr = __expf(m - s);
                ssum *= corr;
                u64 cp = pack2(corr, corr);
                #pragma unroll
                for (int d = 0; d < 16; d++) mul2(accp[d], cp);
                m = s;
                p = 1.f;
            }
            ssum += p;
            u64 pp = pack2(p, p);
            #pragma unroll
            for (int pq = 0; pq < 8; pq++) {
                ulonglong2 vv = *(const ulonglong2*)&Vsh[j][pq*4];
                fma2(accp[2*pq],   pp, vv.x);
                fma2(accp[2*pq+1], pp, vv.y);
            }
        }
        __syncthreads();
    }
    float inv = 1.f / ssum;
    float* op = o + (size_t)(b*Tt + qi)*Cc + h*HSs;
    #pragma unroll
    for (int d = 0; d < 16; d++) {
        float2 v = unpack2(accp[d]);
        op[2*d]   = v.x * inv;
        op[2*d+1] = v.y * inv;
    }
}

// ---------------- loss ----------------
__global__ void zero_loss_k() { g_loss = 0.f; }

__global__ __launch_bounds__(256) void loss_k(const float* __restrict__ logits,
                                              const int* __restrict__ targets) {
    int row = blockIdx.x;
    const float* lr = logits + (size_t)row * Vv;
    float mx = -1e30f;
    for (int i = threadIdx.x; i < Vv; i += 256) mx = fmaxf(mx, lr[i]);
    for (int o = 16; o > 0; o >>= 1) mx = fmaxf(mx, __shfl_down_sync(0xffffffff, mx, o));
    __shared__ float shm[8];
    int wid = threadIdx.x >> 5, lane = threadIdx.x & 31;
    if (lane == 0) shm[wid] = mx;
    __syncthreads();
    __shared__ float rowmax;
    if (threadIdx.x == 0) {
        float t = shm[0];
        for (int i = 1; i < 8; i++) t = fmaxf(t, shm[i]);
        rowmax = t;
    }
    __syncthreads();
    float rm = rowmax;
    float se = 0.f;
    for (int i = threadIdx.x; i < Vv; i += 256) se += __expf(lr[i] - rm);
    for (int o = 16; o > 0; o >>= 1) se += __shfl_down_sync(0xffffffff, se, o);
    if (lane == 0) shm[wid] = se;
    __syncthreads();
    if (threadIdx.x == 0) {
        float t = 0.f;
        for (int i = 0; i < 8; i++) t += shm[i];
        float lp = lr[targets[row]] - rm - logf(t);
        atomicAdd(&g_loss, lp);
    }
}

__global__ void finalize_k(float* out, int extra) {
    float lv = -g_loss / (float)BT;
    for (int i = threadIdx.x + blockIdx.x*blockDim.x; i < extra; i += blockDim.x*gridDim.x)
        out[BTV + i] = lv;
}

// ---------------- host launcher ----------------
static void* symaddr(const void* sym) {
    void* p = nullptr;
    cudaGetSymbolAddress(&p, sym);
    return p;
}

extern "C" void kernel_launch(void* const* d_in, const int* in_sizes, int n_in,
                              void* d_out, int out_size) {
    const int*   idx      = (const int*)  d_in[0];
    const int*   idx_lab  = (const int*)  d_in[1];
    const int*   targets  = (const int*)  d_in[2];
    const float* tok_emb  = (const float*)d_in[3];
    const float* pos_emb  = (const float*)d_in[4];
    const float* lab_emb  = (const float*)d_in[5];
    const float* Wq       = (const float*)d_in[6];
    const float* Wk       = (const float*)d_in[7];
    const float* Wv       = (const float*)d_in[8];
    const float* Wo       = (const float*)d_in[9];
    const float* bo       = (const float*)d_in[10];
    const float* ln1_g    = (const float*)d_in[11];
    const float* ln1_b    = (const float*)d_in[12];
    const float* W1       = (const float*)d_in[13];
    const float* b1       = (const float*)d_in[14];
    const float* W2       = (const float*)d_in[15];
    const float* b2       = (const float*)d_in[16];
    const float* ln2_g    = (const float*)d_in[17];
    const float* ln2_b    = (const float*)d_in[18];
    const float* lnf_g    = (const float*)d_in[19];
    const float* lnf_b    = (const float*)d_in[20];
    const float* Wlm      = (const float*)d_in[21];
    const float* blm      = (const float*)d_in[22];
    float* out = (float*)d_out;

    float* x   = (float*)symaddr(g_x);
    float* h   = (float*)symaddr(g_h);
    float* qkv = (float*)symaddr(g_qkv);
    float* o   = (float*)symaddr(g_o);
    float* ff  = (float*)symaddr(g_ff);
    __half* wqkv_h = (__half*)symaddr(g_wqkv_h);
    __half* wqkv_l = (__half*)symaddr(g_wqkv_l);
    __half* wo_h   = (__half*)symaddr(g_wo_h);
    __half* wo_l   = (__half*)symaddr(g_wo_l);
    __half* w1_h   = (__half*)symaddr(g_w1_h);
    __half* w1_l   = (__half*)symaddr(g_w1_l);
    __half* w2_h   = (__half*)symaddr(g_w2_h);
    __half* w2_l   = (__half*)symaddr(g_w2_l);
    __half* wlm_h  = (__half*)symaddr(g_wlm_h);
    __half* wlm_l  = (__half*)symaddr(g_wlm_l);

    const int SMEM = 2 * BUFH * (int)sizeof(__half);   // 81920
    cudaFuncSetAttribute(hgemm_k<false,false,false>, cudaFuncAttributeMaxDynamicSharedMemorySize, SMEM);
    cudaFuncSetAttribute(hgemm_k<true,false,true>,   cudaFuncAttributeMaxDynamicSharedMemorySize, SMEM);
    cudaFuncSetAttribute(hgemm_k<true,true,false>,   cudaFuncAttributeMaxDynamicSharedMemorySize, SMEM);
    cudaFuncSetAttribute(hgemm_k<true,false,false>,  cudaFuncAttributeMaxDynamicSharedMemorySize, SMEM);

    dim3 tb(32, 8);
    pack_qkv_split<<<dim3(16, 16, 12), tb>>>(Wq, Wk, Wv);
    tsplit_k<<<dim3(16, 16, 12), tb>>>(Wo,  wo_h,  wo_l,  Cc,  Cc);
    tsplit_k<<<dim3(64, 16, 12), tb>>>(W1,  w1_h,  w1_l,  Cc,  FFf);
    tsplit_k<<<dim3(16, 64, 12), tb>>>(W2,  w2_h,  w2_l,  FFf, Cc);
    tsplit_k<<<dim3(256, 16, 1), tb>>>(Wlm, wlm_h, wlm_l, Cc,  Vv);

    embed_k<<<BT, 128>>>(idx, idx_lab, tok_emb, lab_emb, pos_emb);

    dim3 gQKV(NQKV/128, BT/128);
    dim3 g512(Cc/128,   BT/128);
    dim3 g2048(FFf/128, BT/128);
    dim3 gV(Vv/128,     BT/128);
    dim3 gattn(Tt/128, Bb*Hh);

    for (int l = 0; l < Ll; l++) {
        lnorm_k<<<BT, 128>>>(x, ln1_g + l*Cc, ln1_b + l*Cc, h);
        hgemm_k<false,false,false><<<gQKV, 256, SMEM>>>(h, wqkv_h + (size_t)l*NQKV*Cc,
                                                  wqkv_l + (size_t)l*NQKV*Cc,
                                                  nullptr, nullptr, qkv, BT, NQKV, Cc);
        attn_k<<<gattn, 128>>>(qkv, o);
        hgemm_k<true,false,true><<<g512, 256, SMEM>>>(o, wo_h + (size_t)l*Cc*Cc,
                                                wo_l + (size_t)l*Cc*Cc,
                                                bo + l*Cc, x, x, BT, Cc, Cc);
        lnorm_k<<<BT, 128>>>(x, ln2_g + l*Cc, ln2_b + l*Cc, h);
        hgemm_k<true,true,false><<<g2048, 256, SMEM>>>(h, w1_h + (size_t)l*FFf*Cc,
                                                 w1_l + (size_t)l*FFf*Cc,
                                                 b1 + l*FFf, nullptr, ff, BT, FFf, Cc);
        hgemm_k<true,false,true><<<g512, 256, SMEM>>>(ff, w2_h + (size_t)l*Cc*FFf,
                                                w2_l + (size_t)l*Cc*FFf,
                                                b2 + l*Cc, x, x, BT, Cc, FFf);
    }
    lnorm_k<<<BT, 128>>>(x, lnf_g, lnf_b, h);
    hgemm_k<true,false,false><<<gV, 256, SMEM>>>(h, wlm_h, wlm_l, blm, nullptr, out, BT, Vv, Cc);

    zero_loss_k<<<1, 1>>>();
    loss_k<<<BT, 256>>>(out, targets);
    int extra = out_size - (int)BTV;
    if (extra > 0) finalize_k<<<1, 128>>>(out, extra);
}